// round 3
// baseline (speedup 1.0000x reference)
#include <cuda_runtime.h>

#define SIZE_ 50000
#define NS_   32
#define OUT_  64
#define MID_  8
#define NTOT  (SIZE_*NS_)
#define EPS_  1e-5f

// ---- device scratch (no runtime allocation allowed) ----
__device__ float g_stats[4];            // sum t0, sum t1, sum t0^2, sum t1^2
__device__ float g_const[32];           // [0..3] A (BN-folded W_p1), [4..5] c, [6..13] M0, [14..21] M1, [22..29] bq_eff
__device__ float g_gsum[SIZE_ * MID_];  // sum of exp(q) per (segment, m)
__device__ float g_num [SIZE_ * MID_];  // sum of v*exp(q) per (segment, m)

typedef unsigned long long ull;

__device__ __forceinline__ ull fma2(ull a, ull b, ull c) {
    ull d;
    asm("fma.rn.f32x2 %0, %1, %2, %3;" : "=l"(d) : "l"(a), "l"(b), "l"(c));
    return d;
}
__device__ __forceinline__ float lo_add_hi(ull a) {
    return __uint_as_float((unsigned)(a & 0xffffffffull)) +
           __uint_as_float((unsigned)(a >> 32));
}

// ---------------------------------------------------------------------------
// Kernel 1: BN batch statistics of t = translation @ W_p1^T
// ---------------------------------------------------------------------------
__global__ void stats_kernel(const float2* __restrict__ trans,
                             const float* __restrict__ Wp1) {
    const float w00 = Wp1[0], w01 = Wp1[1], w10 = Wp1[2], w11 = Wp1[3];
    float s0 = 0.f, s1 = 0.f, q0 = 0.f, q1 = 0.f;
    int stride = gridDim.x * blockDim.x;
    for (int i = blockIdx.x * blockDim.x + threadIdx.x; i < NTOT; i += stride) {
        float2 tr = trans[i];
        float t0 = tr.x * w00 + tr.y * w01;
        float t1 = tr.x * w10 + tr.y * w11;
        s0 += t0; s1 += t1; q0 += t0 * t0; q1 += t1 * t1;
    }
    #pragma unroll
    for (int d = 16; d > 0; d >>= 1) {
        s0 += __shfl_xor_sync(0xffffffffu, s0, d);
        s1 += __shfl_xor_sync(0xffffffffu, s1, d);
        q0 += __shfl_xor_sync(0xffffffffu, q0, d);
        q1 += __shfl_xor_sync(0xffffffffu, q1, d);
    }
    if ((threadIdx.x & 31) == 0) {
        atomicAdd(&g_stats[0], s0);
        atomicAdd(&g_stats[1], s1);
        atomicAdd(&g_stats[2], q0);
        atomicAdd(&g_stats[3], q1);
    }
}

// ---------------------------------------------------------------------------
// Kernel 2: fold everything linear into tiny constants
//   tn_j = (trans . A_j) + c_j      (BN folded into W_p1)
//   q   += relu(tn0)*M0[m] + relu(tn1)*M1[m] + bq_eff[m]
// ---------------------------------------------------------------------------
__global__ void prep_kernel(const float* __restrict__ Wq,  const float* __restrict__ bq,
                            const float* __restrict__ Wp1, const float* __restrict__ gamma,
                            const float* __restrict__ beta, const float* __restrict__ Wp2,
                            const float* __restrict__ bp2) {
    int t = threadIdx.x;
    int w = t >> 5, l = t & 31;
    if (w < 8) {
        int m = w;
        float m0 = 0.f, m1 = 0.f, pb = 0.f;
        for (int c = l; c < OUT_; c += 32) {
            float wq = Wq[m * OUT_ + c];
            m0 += Wp2[c * 2 + 0] * wq;
            m1 += Wp2[c * 2 + 1] * wq;
            pb += bp2[c] * wq;
        }
        #pragma unroll
        for (int d = 16; d > 0; d >>= 1) {
            m0 += __shfl_xor_sync(0xffffffffu, m0, d);
            m1 += __shfl_xor_sync(0xffffffffu, m1, d);
            pb += __shfl_xor_sync(0xffffffffu, pb, d);
        }
        if (l == 0) {
            g_const[6 + m]  = m0;
            g_const[14 + m] = m1;
            g_const[22 + m] = bq[m] + pb;
        }
    }
    if (t == 255) {
        const float invN = 1.0f / (float)NTOT;
        #pragma unroll
        for (int j = 0; j < 2; j++) {
            float mean = g_stats[j] * invN;
            float var  = g_stats[2 + j] * invN - mean * mean;
            float s    = gamma[j] * rsqrtf(var + EPS_);
            g_const[j * 2 + 0] = Wp1[j * 2 + 0] * s;
            g_const[j * 2 + 1] = Wp1[j * 2 + 1] * s;
            g_const[4 + j]     = beta[j] - mean * s;
        }
    }
}

// ---------------------------------------------------------------------------
// Kernel 3: the fused main pass.
//   Block = 128 threads, 4 sets (128 rows). One read of `outputs`:
//     - features (per-set column sums) -> written directly to d_out
//     - q[8], v[8] per row via f32x2 FMAs (weights broadcast from smem)
//     - e = exp(q); atomicAdd gsum += e, num += v*e at segment idx
// ---------------------------------------------------------------------------
__global__ __launch_bounds__(128)
void main_kernel(const float* __restrict__ outputs,
                 const float2* __restrict__ trans,
                 const int* __restrict__ idxs,
                 const float* __restrict__ Wq,
                 const float* __restrict__ Wv,
                 const float* __restrict__ bv,
                 float* __restrict__ out) {
    __shared__ float xt[128 * 68];     // tile, stride-68 pad: conflict-free LDS.128
    __shared__ float wsm[16 * 64];     // rows 0..7 = W_q, 8..15 = W_v
    __shared__ float sfeat[8 * 256];   // feature partials
    __shared__ float csm[40];          // folded constants + b_v

    const int t   = threadIdx.x;
    const int bid = blockIdx.x;

    // stage weights + constants
    ((float4*)wsm)[t]       = ((const float4*)Wq)[t & 127];
    ((float4*)wsm)[128 + t] = ((const float4*)Wv)[t & 127];
    if (t < 30)            csm[t] = g_const[t];
    else if (t < 38)       csm[t] = bv[t - 30];

    // coalesced global -> smem tile, fused per-set column partial sums
    const float4* src = (const float4*)outputs + (size_t)bid * 2048;
    const int a = t >> 4, b = t & 15;
    float facc[4][4];
    #pragma unroll
    for (int s = 0; s < 4; s++)
        #pragma unroll
        for (int i = 0; i < 4; i++) facc[s][i] = 0.f;

    #pragma unroll
    for (int j = 0; j < 16; j++) {
        float4 v = src[t + 128 * j];
        const int s = j >> 2;
        const int trow = 32 * s + 8 * (j & 3) + a;
        *(float4*)(&xt[trow * 68 + 4 * b]) = v;
        facc[s][0] += v.x; facc[s][1] += v.y; facc[s][2] += v.z; facc[s][3] += v.w;
    }
    #pragma unroll
    for (int s = 0; s < 4; s++)
        *(float4*)(&sfeat[a * 256 + s * 64 + 4 * b]) =
            make_float4(facc[s][0], facc[s][1], facc[s][2], facc[s][3]);

    __syncthreads();

    // features -> d_out (residual added by finalize kernel)
    #pragma unroll
    for (int p = t; p < 256; p += 128) {
        float f = 0.f;
        #pragma unroll
        for (int aa = 0; aa < 8; aa++) f += sfeat[aa * 256 + p];
        out[((size_t)bid * 4 + (p >> 6)) * 64 + (p & 63)] = f;
    }

    // per-row q/v: 512 f32x2 FMAs, weights via broadcast LDS
    ull acc[16];
    #pragma unroll
    for (int o = 0; o < 16; o++) acc[o] = 0ull;

    const float* xr = &xt[t * 68];
    #pragma unroll 2
    for (int c = 0; c < 8; c++) {
        ulonglong2 X0 = *(const ulonglong2*)(xr + c * 8);
        ulonglong2 X1 = *(const ulonglong2*)(xr + c * 8 + 4);
        #pragma unroll
        for (int o = 0; o < 16; o++) {
            ulonglong2 W0 = *(const ulonglong2*)(wsm + o * 64 + c * 8);
            ulonglong2 W1 = *(const ulonglong2*)(wsm + o * 64 + c * 8 + 4);
            acc[o] = fma2(X0.x, W0.x, acc[o]);
            acc[o] = fma2(X0.y, W0.y, acc[o]);
            acc[o] = fma2(X1.x, W1.x, acc[o]);
            acc[o] = fma2(X1.y, W1.y, acc[o]);
        }
    }

    const int gn = bid * 128 + t;
    float2 tr = trans[gn];
    float tn0 = tr.x * csm[0] + tr.y * csm[1] + csm[4];
    float tn1 = tr.x * csm[2] + tr.y * csm[3] + csm[5];
    float r0 = fmaxf(tn0, 0.f), r1 = fmaxf(tn1, 0.f);

    const int idx = idxs[gn];
    float* gs = g_gsum + (size_t)idx * 8;
    float* gm = g_num  + (size_t)idx * 8;

    #pragma unroll
    for (int o = 0; o < 8; o++) {
        float q = lo_add_hi(acc[o]) + r0 * csm[6 + o] + r1 * csm[14 + o] + csm[22 + o];
        float v = lo_add_hi(acc[8 + o]) + csm[30 + o];
        float e = expf(q);          // no max-shift needed: q bounded, softmax shift-invariant
        atomicAdd(gs + o, e);
        atomicAdd(gm + o, v * e);
    }
}

// ---------------------------------------------------------------------------
// Kernel 4: out[i,c] = features[i,c] + num[i,c%8]/gsum[i,c%8]
// ---------------------------------------------------------------------------
__global__ void finalize_kernel(float* __restrict__ out) {
    int i = blockIdx.x * blockDim.x + threadIdx.x;
    if (i < SIZE_ * OUT_) {
        int s = i >> 6, m = i & 7;
        float gs = g_gsum[s * 8 + m];
        float r  = (gs != 0.f) ? g_num[s * 8 + m] / gs : 0.f;
        out[i] += r;
    }
}

// ---------------------------------------------------------------------------
extern "C" void kernel_launch(void* const* d_in, const int* in_sizes, int n_in,
                              void* d_out, int out_size) {
    const float*  outputs = (const float*)d_in[0];
    const float2* trans   = (const float2*)d_in[1];
    const int*    idxs    = (const int*)d_in[2];
    const float*  Wq      = (const float*)d_in[3];
    const float*  bq      = (const float*)d_in[4];
    const float*  Wv      = (const float*)d_in[5];
    const float*  bv      = (const float*)d_in[6];
    const float*  Wp1     = (const float*)d_in[7];
    const float*  gamma   = (const float*)d_in[8];
    const float*  beta    = (const float*)d_in[9];
    const float*  Wp2     = (const float*)d_in[10];
    const float*  bp2     = (const float*)d_in[11];
    float* out = (float*)d_out;

    void* p;
    cudaGetSymbolAddress(&p, g_stats);
    cudaMemsetAsync(p, 0, 4 * sizeof(float));
    cudaGetSymbolAddress(&p, g_gsum);
    cudaMemsetAsync(p, 0, SIZE_ * MID_ * sizeof(float));
    cudaGetSymbolAddress(&p, g_num);
    cudaMemsetAsync(p, 0, SIZE_ * MID_ * sizeof(float));

    stats_kernel<<<1024, 256>>>(trans, Wp1);
    prep_kernel<<<1, 256>>>(Wq, bq, Wp1, gamma, beta, Wp2, bp2);
    main_kernel<<<SIZE_ / 4, 128>>>(outputs, trans, idxs, Wq, Wv, bv, out);
    finalize_kernel<<<(SIZE_ * OUT_ + 255) / 256, 256>>>(out);
}

// round 4
// speedup vs baseline: 1.2365x; 1.2365x over previous
#include <cuda_runtime.h>

#define SIZE_ 50000
#define NS_   32
#define OUT_  64
#define MID_  8
#define NTOT  (SIZE_*NS_)
#define EPS_  1e-5f

// ---- device scratch (no runtime allocation allowed) ----
__device__ float g_stats[4];      // sum t0, sum t1, sum t0^2, sum t1^2
__device__ float g_const[32];     // [0..3] A (BN-folded W_p1), [4..5] c, [6..13] M0, [14..21] M1, [22..29] bq_eff
// per segment: [0..7] = sum e, [8..15] = sum v*e  (ratio kernel overwrites [0..7] with num/den)
__device__ __align__(64) float g_acc[SIZE_ * 16];

typedef unsigned long long ull;

__device__ __forceinline__ ull fma2(ull a, ull b, ull c) {
    ull d;
    asm("fma.rn.f32x2 %0, %1, %2, %3;" : "=l"(d) : "l"(a), "l"(b), "l"(c));
    return d;
}
__device__ __forceinline__ float lo_add_hi(ull a) {
    return __uint_as_float((unsigned)(a & 0xffffffffull)) +
           __uint_as_float((unsigned)(a >> 32));
}
__device__ __forceinline__ void red_add_v4(float* p, float a, float b, float c, float d) {
    asm volatile("red.global.add.v4.f32 [%0], {%1, %2, %3, %4};"
                 :: "l"(p), "f"(a), "f"(b), "f"(c), "f"(d) : "memory");
}

// ---------------------------------------------------------------------------
// Kernel 1: BN batch statistics of t = translation @ W_p1^T
// ---------------------------------------------------------------------------
__global__ void stats_kernel(const float2* __restrict__ trans,
                             const float* __restrict__ Wp1) {
    const float w00 = Wp1[0], w01 = Wp1[1], w10 = Wp1[2], w11 = Wp1[3];
    float s0 = 0.f, s1 = 0.f, q0 = 0.f, q1 = 0.f;
    int stride = gridDim.x * blockDim.x;
    for (int i = blockIdx.x * blockDim.x + threadIdx.x; i < NTOT; i += stride) {
        float2 tr = trans[i];
        float t0 = tr.x * w00 + tr.y * w01;
        float t1 = tr.x * w10 + tr.y * w11;
        s0 += t0; s1 += t1; q0 += t0 * t0; q1 += t1 * t1;
    }
    #pragma unroll
    for (int d = 16; d > 0; d >>= 1) {
        s0 += __shfl_xor_sync(0xffffffffu, s0, d);
        s1 += __shfl_xor_sync(0xffffffffu, s1, d);
        q0 += __shfl_xor_sync(0xffffffffu, q0, d);
        q1 += __shfl_xor_sync(0xffffffffu, q1, d);
    }
    if ((threadIdx.x & 31) == 0) {
        atomicAdd(&g_stats[0], s0);
        atomicAdd(&g_stats[1], s1);
        atomicAdd(&g_stats[2], q0);
        atomicAdd(&g_stats[3], q1);
    }
}

// ---------------------------------------------------------------------------
// Kernel 2: fold everything linear into tiny constants
// ---------------------------------------------------------------------------
__global__ void prep_kernel(const float* __restrict__ Wq,  const float* __restrict__ bq,
                            const float* __restrict__ Wp1, const float* __restrict__ gamma,
                            const float* __restrict__ beta, const float* __restrict__ Wp2,
                            const float* __restrict__ bp2) {
    int t = threadIdx.x;
    int w = t >> 5, l = t & 31;
    if (w < 8) {
        int m = w;
        float m0 = 0.f, m1 = 0.f, pb = 0.f;
        for (int c = l; c < OUT_; c += 32) {
            float wq = Wq[m * OUT_ + c];
            m0 += Wp2[c * 2 + 0] * wq;
            m1 += Wp2[c * 2 + 1] * wq;
            pb += bp2[c] * wq;
        }
        #pragma unroll
        for (int d = 16; d > 0; d >>= 1) {
            m0 += __shfl_xor_sync(0xffffffffu, m0, d);
            m1 += __shfl_xor_sync(0xffffffffu, m1, d);
            pb += __shfl_xor_sync(0xffffffffu, pb, d);
        }
        if (l == 0) {
            g_const[6 + m]  = m0;
            g_const[14 + m] = m1;
            g_const[22 + m] = bq[m] + pb;
        }
    }
    if (t == 255) {
        const float invN = 1.0f / (float)NTOT;
        #pragma unroll
        for (int j = 0; j < 2; j++) {
            float mean = g_stats[j] * invN;
            float var  = g_stats[2 + j] * invN - mean * mean;
            float s    = gamma[j] * rsqrtf(var + EPS_);
            g_const[j * 2 + 0] = Wp1[j * 2 + 0] * s;
            g_const[j * 2 + 1] = Wp1[j * 2 + 1] * s;
            g_const[4 + j]     = beta[j] - mean * s;
        }
    }
}

// ---------------------------------------------------------------------------
// Kernel 3: fused main pass. 128 threads, 4 sets (128 rows) per block.
//   One read of `outputs`: features -> out, q/v via f32x2 FMAs,
//   vectorized red.v4 accumulation of (e, v*e) per segment.
// ---------------------------------------------------------------------------
__global__ __launch_bounds__(128)
void main_kernel(const float* __restrict__ outputs,
                 const float2* __restrict__ trans,
                 const int* __restrict__ idxs,
                 const float* __restrict__ Wq,
                 const float* __restrict__ Wv,
                 const float* __restrict__ bv,
                 float* __restrict__ out) {
    __shared__ float xt[128 * 68];     // stride-68 pad: conflict-free LDS.128
    __shared__ float wsm[16 * 64];     // rows 0..7 = W_q, 8..15 = W_v
    __shared__ float sfeat[8 * 256];
    __shared__ float csm[40];

    const int t   = threadIdx.x;
    const int bid = blockIdx.x;

    ((float4*)wsm)[t]       = ((const float4*)Wq)[t & 127];
    ((float4*)wsm)[128 + t] = ((const float4*)Wv)[t & 127];
    if (t < 30)            csm[t] = g_const[t];
    else if (t < 38)       csm[t] = bv[t - 30];

    const float4* src = (const float4*)outputs + (size_t)bid * 2048;
    const int a = t >> 4, b = t & 15;
    float facc[4][4];
    #pragma unroll
    for (int s = 0; s < 4; s++)
        #pragma unroll
        for (int i = 0; i < 4; i++) facc[s][i] = 0.f;

    #pragma unroll
    for (int j = 0; j < 16; j++) {
        float4 v = src[t + 128 * j];
        const int s = j >> 2;
        const int trow = 32 * s + 8 * (j & 3) + a;
        *(float4*)(&xt[trow * 68 + 4 * b]) = v;
        facc[s][0] += v.x; facc[s][1] += v.y; facc[s][2] += v.z; facc[s][3] += v.w;
    }
    #pragma unroll
    for (int s = 0; s < 4; s++)
        *(float4*)(&sfeat[a * 256 + s * 64 + 4 * b]) =
            make_float4(facc[s][0], facc[s][1], facc[s][2], facc[s][3]);

    __syncthreads();

    // features -> d_out (residual added by finalize)
    #pragma unroll
    for (int p = t; p < 256; p += 128) {
        float f = 0.f;
        #pragma unroll
        for (int aa = 0; aa < 8; aa++) f += sfeat[aa * 256 + p];
        out[((size_t)bid * 4 + (p >> 6)) * 64 + (p & 63)] = f;
    }

    // per-row q/v: 512 f32x2 FMAs, weights broadcast from smem
    ull acc[16];
    #pragma unroll
    for (int o = 0; o < 16; o++) acc[o] = 0ull;

    const float* xr = &xt[t * 68];
    #pragma unroll 2
    for (int c = 0; c < 8; c++) {
        ulonglong2 X0 = *(const ulonglong2*)(xr + c * 8);
        ulonglong2 X1 = *(const ulonglong2*)(xr + c * 8 + 4);
        #pragma unroll
        for (int o = 0; o < 16; o++) {
            ulonglong2 W0 = *(const ulonglong2*)(wsm + o * 64 + c * 8);
            ulonglong2 W1 = *(const ulonglong2*)(wsm + o * 64 + c * 8 + 4);
            acc[o] = fma2(X0.x, W0.x, acc[o]);
            acc[o] = fma2(X0.y, W0.y, acc[o]);
            acc[o] = fma2(X1.x, W1.x, acc[o]);
            acc[o] = fma2(X1.y, W1.y, acc[o]);
        }
    }

    const int gn = bid * 128 + t;
    float2 tr = trans[gn];
    float tn0 = tr.x * csm[0] + tr.y * csm[1] + csm[4];
    float tn1 = tr.x * csm[2] + tr.y * csm[3] + csm[5];
    float r0 = fmaxf(tn0, 0.f), r1 = fmaxf(tn1, 0.f);

    float e[8], ve[8];
    #pragma unroll
    for (int o = 0; o < 8; o++) {
        float q = lo_add_hi(acc[o]) + r0 * csm[6 + o] + r1 * csm[14 + o] + csm[22 + o];
        float v = lo_add_hi(acc[8 + o]) + csm[30 + o];
        e[o]  = __expf(q);   // softmax is shift-invariant; q bounded -> no max pass
        ve[o] = v * e[o];
    }

    float* base = g_acc + (size_t)idxs[gn] * 16;
    red_add_v4(base,      e[0],  e[1],  e[2],  e[3]);
    red_add_v4(base + 4,  e[4],  e[5],  e[6],  e[7]);
    red_add_v4(base + 8,  ve[0], ve[1], ve[2], ve[3]);
    red_add_v4(base + 12, ve[4], ve[5], ve[6], ve[7]);
}

// ---------------------------------------------------------------------------
// Kernel 4a: per-segment ratio r[m] = num[m]/den[m], overwrites g_acc[s*16+m]
// ---------------------------------------------------------------------------
__global__ void ratio_kernel() {
    int i = blockIdx.x * blockDim.x + threadIdx.x;   // SIZE_*2 float4 chunks
    if (i < SIZE_ * 2) {
        int s = i >> 1, k = i & 1;
        float4 den = *(float4*)(g_acc + s * 16 + k * 4);
        float4 num = *(float4*)(g_acc + s * 16 + 8 + k * 4);
        float4 r;
        r.x = (den.x != 0.f) ? num.x / den.x : 0.f;
        r.y = (den.y != 0.f) ? num.y / den.y : 0.f;
        r.z = (den.z != 0.f) ? num.z / den.z : 0.f;
        r.w = (den.w != 0.f) ? num.w / den.w : 0.f;
        *(float4*)(g_acc + s * 16 + k * 4) = r;
    }
}

// ---------------------------------------------------------------------------
// Kernel 4b: out[s, c] += r[s, c%8], 8 elements per thread, float4 ops
// ---------------------------------------------------------------------------
__global__ void finalize_kernel(float* __restrict__ out) {
    int i = blockIdx.x * blockDim.x + threadIdx.x;   // SIZE_*8 chunks of 8 floats
    if (i < SIZE_ * 8) {
        int s = i >> 3;
        float4 r0 = *(float4*)(g_acc + s * 16);
        float4 r1 = *(float4*)(g_acc + s * 16 + 4);
        float4* o = (float4*)(out + (size_t)i * 8);
        float4 a = o[0], b = o[1];
        a.x += r0.x; a.y += r0.y; a.z += r0.z; a.w += r0.w;
        b.x += r1.x; b.y += r1.y; b.z += r1.z; b.w += r1.w;
        o[0] = a; o[1] = b;
    }
}

// ---------------------------------------------------------------------------
extern "C" void kernel_launch(void* const* d_in, const int* in_sizes, int n_in,
                              void* d_out, int out_size) {
    const float*  outputs = (const float*)d_in[0];
    const float2* trans   = (const float2*)d_in[1];
    const int*    idxs    = (const int*)d_in[2];
    const float*  Wq      = (const float*)d_in[3];
    const float*  bq      = (const float*)d_in[4];
    const float*  Wv      = (const float*)d_in[5];
    const float*  bv      = (const float*)d_in[6];
    const float*  Wp1     = (const float*)d_in[7];
    const float*  gamma   = (const float*)d_in[8];
    const float*  beta    = (const float*)d_in[9];
    const float*  Wp2     = (const float*)d_in[10];
    const float*  bp2     = (const float*)d_in[11];
    float* out = (float*)d_out;

    void* p;
    cudaGetSymbolAddress(&p, g_stats);
    cudaMemsetAsync(p, 0, 4 * sizeof(float));
    cudaGetSymbolAddress(&p, g_acc);
    cudaMemsetAsync(p, 0, SIZE_ * 16 * sizeof(float));

    stats_kernel<<<1024, 256>>>(trans, Wp1);
    prep_kernel<<<1, 256>>>(Wq, bq, Wp1, gamma, beta, Wp2, bp2);
    main_kernel<<<SIZE_ / 4, 128>>>(outputs, trans, idxs, Wq, Wv, bv, out);
    ratio_kernel<<<(SIZE_ * 2 + 255) / 256, 256>>>();
    finalize_kernel<<<(SIZE_ * 8 + 255) / 256, 256>>>(out);
}